// round 2
// baseline (speedup 1.0000x reference)
#include <cuda_runtime.h>
#include <cstdint>

// Problem constants
#define B_    64
#define P_    56
#define N_    3136      // P*P
#define DIM_  256
#define HEADS_ 4
#define HD_   24
#define M_    16
#define OUT_  256
#define BH_   256       // B*HEADS

// ---------------- scratch (no allocation allowed; __device__ globals) ----------------
__device__ float g_f[(size_t)BH_ * N_ * HD_];            // [bh][n][hd]
__device__ float g_v[(size_t)BH_ * N_ * HD_];            // [bh][n][hd]
__device__ float g_centers_n[BH_ * M_ * HD_];            // normalized centers
__device__ float g_value_centers[BH_ * M_ * HD_];
__device__ float g_agg[BH_ * M_ * HD_];
__device__ int   g_assign[(size_t)BH_ * N_];
__device__ float g_sval[(size_t)BH_ * N_];

// =====================================================================
// K1: fused feat/val GEMM.  out[r, 0..191] = x[r,:] @ [f_w; v_w]^T + bias
// Tile: 64 rows x 192 cols, 256 threads, 8x6 per thread, K-chunk 32.
// Smem stride 36 so float4 k-loads are aligned + conflict-free:
//   bank start of lane l = (4*l + kk) mod 32 -> distinct 4-bank ranges.
// =====================================================================
__global__ __launch_bounds__(256) void k_gemm_fv(
    const float* __restrict__ x,
    const float* __restrict__ f_w, const float* __restrict__ f_b,
    const float* __restrict__ v_w, const float* __restrict__ v_b)
{
    __shared__ float Xs[64][36];     // [row][k]
    __shared__ float Ws[192][36];    // [col][k]

    const int tid = threadIdx.x;
    const int tx = tid & 31;          // col lane
    const int ty = tid >> 5;          // warp id -> row group (uniform per warp)
    const int r0 = blockIdx.x * 64;
    const int bb = r0 / N_;

    float acc[8][6];
#pragma unroll
    for (int i = 0; i < 8; i++)
#pragma unroll
        for (int j = 0; j < 6; j++) acc[i][j] = 0.f;

    for (int kc = 0; kc < DIM_; kc += 32) {
        // X tile: 64x32 = 512 float4
#pragma unroll
        for (int l = tid; l < 512; l += 256) {
            int row = l >> 3, q = l & 7;
            float4 t = *(const float4*)(x + (size_t)(r0 + row) * DIM_ + kc + q * 4);
            *(float4*)&Xs[row][q * 4] = t;
        }
        // W tile: 192x32 = 1536 float4 (rows 0..95 f_w, 96..191 v_w)
#pragma unroll
        for (int l = tid; l < 1536; l += 256) {
            int row = l >> 3, q = l & 7;
            const float* src = (row < 96) ? (f_w + (size_t)row * DIM_)
                                          : (v_w + (size_t)(row - 96) * DIM_);
            *(float4*)&Ws[row][q * 4] = *(const float4*)(src + kc + q * 4);
        }
        __syncthreads();
#pragma unroll
        for (int kk = 0; kk < 32; kk += 4) {
            float a[8][4], w[6][4];
#pragma unroll
            for (int i = 0; i < 8; i++) {                       // warp-uniform: broadcast
                float4 t = *(const float4*)&Xs[i * 8 + ty][kk];
                a[i][0] = t.x; a[i][1] = t.y; a[i][2] = t.z; a[i][3] = t.w;
            }
#pragma unroll
            for (int j = 0; j < 6; j++) {                       // conflict-free LDS.128
                float4 t = *(const float4*)&Ws[j * 32 + tx][kk];
                w[j][0] = t.x; w[j][1] = t.y; w[j][2] = t.z; w[j][3] = t.w;
            }
#pragma unroll
            for (int s = 0; s < 4; s++)
#pragma unroll
                for (int i = 0; i < 8; i++)
#pragma unroll
                    for (int j = 0; j < 6; j++)
                        acc[i][j] = fmaf(a[i][s], w[j][s], acc[i][j]);
        }
        __syncthreads();
    }

    // scatter into head-split layout
#pragma unroll
    for (int i = 0; i < 8; i++) {
        int r = r0 + i * 8 + ty;
        int n = r - bb * N_;
#pragma unroll
        for (int j = 0; j < 6; j++) {
            int col = j * 32 + tx;
            if (col < 96) {
                int e = col / HD_, c = col % HD_;
                g_f[((size_t)(bb * HEADS_ + e) * N_ + n) * HD_ + c] = acc[i][j] + f_b[col];
            } else {
                int col2 = col - 96;
                int e = col2 / HD_, c = col2 % HD_;
                g_v[((size_t)(bb * HEADS_ + e) * N_ + n) * HD_ + c] = acc[i][j] + v_b[col2];
            }
        }
    }
}

// =====================================================================
// K2: adaptive-avg-pool to (4,4) + L2-normalize centers.
// =====================================================================
__global__ __launch_bounds__(192) void k_pool()
{
    __shared__ float sf[192], sv[192];
    __shared__ float cf[24];
    __shared__ float norm_inv;

    const int g  = blockIdx.x;
    const int bh = g >> 4;
    const int m  = g & 15;
    const int pw = m >> 2, ph = m & 3;
    const int tid = threadIdx.x;
    const int c = tid % 24, part = tid / 24;

    float af = 0.f, av = 0.f;
    for (int it = part; it < 196; it += 8) {
        int dw = it / 14, dh = it % 14;
        int n = (pw * 14 + dw) * P_ + ph * 14 + dh;
        size_t idx = ((size_t)bh * N_ + n) * HD_ + c;
        af += g_f[idx];
        av += g_v[idx];
    }
    sf[tid] = af; sv[tid] = av;
    __syncthreads();

    if (tid < 24) {
        float s1 = 0.f, s2 = 0.f;
#pragma unroll
        for (int p = 0; p < 8; p++) { s1 += sf[p * 24 + tid]; s2 += sv[p * 24 + tid]; }
        float mf = s1 * (1.f / 196.f);
        float mv = s2 * (1.f / 196.f);
        g_value_centers[(bh * M_ + m) * HD_ + tid] = mv;
        cf[tid] = mf;
    }
    __syncthreads();
    if (tid == 0) {
        float ss = 0.f;
#pragma unroll
        for (int k = 0; k < 24; k++) ss += cf[k] * cf[k];
        norm_inv = 1.f / fmaxf(sqrtf(ss), 1e-12f);
    }
    __syncthreads();
    if (tid < 24)
        g_centers_n[(bh * M_ + m) * HD_ + tid] = cf[tid] * norm_inv;
}

// =====================================================================
// K3: per-bh clustering (assign + aggregate), 1 block per bh.
// =====================================================================
__global__ __launch_bounds__(512) void k_cluster(
    const float* __restrict__ sim_alpha, const float* __restrict__ sim_beta)
{
    __shared__ float cn[M_ * HD_];
    __shared__ unsigned char assign_sh[N_];
    __shared__ float sval_sh[N_];

    const int bh  = blockIdx.x;
    const int tid = threadIdx.x;
    const float alpha = sim_alpha[0];
    const float beta  = sim_beta[0];

    for (int l = tid; l < M_ * HD_; l += 512)
        cn[l] = g_centers_n[bh * M_ * HD_ + l];
    __syncthreads();

    // ---- phase 1: per-token argmax ----
    for (int n = tid; n < N_; n += 512) {
        float fv[24];
        const float4* fp4 = (const float4*)(g_f + ((size_t)bh * N_ + n) * HD_);
#pragma unroll
        for (int q = 0; q < 6; q++) {
            float4 t = fp4[q];
            fv[q * 4 + 0] = t.x; fv[q * 4 + 1] = t.y;
            fv[q * 4 + 2] = t.z; fv[q * 4 + 3] = t.w;
        }
        float ss = 0.f;
#pragma unroll
        for (int k = 0; k < 24; k++) ss += fv[k] * fv[k];
        float inv = 1.f / fmaxf(sqrtf(ss), 1e-12f);

        float best = -3.402823466e38f;
        int bi = 0;
#pragma unroll
        for (int m = 0; m < M_; m++) {
            float d = 0.f;
#pragma unroll
            for (int k = 0; k < 24; k++) d = fmaf(cn[m * HD_ + k], fv[k], d);
            float t = beta + alpha * (d * inv);
            t = (t >= 0.f) ? t : 0.2f * t;
            if (t > best) { best = t; bi = m; }
        }
        assign_sh[n] = (unsigned char)bi;
        sval_sh[n]   = best;
        g_assign[(size_t)bh * N_ + n] = bi;
        g_sval[(size_t)bh * N_ + n]   = best;
    }
    __syncthreads();

    // ---- phase 2: warp per center, atomic-free ----
    const int w    = tid >> 5;
    const int lane = tid & 31;

    float acc[24];
#pragma unroll
    for (int k = 0; k < 24; k++) acc[k] = 0.f;
    int cnt = 0;

    for (int n = lane; n < N_; n += 32) {
        if (assign_sh[n] == (unsigned char)w) {
            float s = sval_sh[n];
            const float4* vp4 = (const float4*)(g_v + ((size_t)bh * N_ + n) * HD_);
#pragma unroll
            for (int q = 0; q < 6; q++) {
                float4 t = vp4[q];
                acc[q * 4 + 0] = fmaf(s, t.x, acc[q * 4 + 0]);
                acc[q * 4 + 1] = fmaf(s, t.y, acc[q * 4 + 1]);
                acc[q * 4 + 2] = fmaf(s, t.z, acc[q * 4 + 2]);
                acc[q * 4 + 3] = fmaf(s, t.w, acc[q * 4 + 3]);
            }
            cnt++;
        }
    }
#pragma unroll
    for (int off = 16; off > 0; off >>= 1) {
#pragma unroll
        for (int k = 0; k < 24; k++)
            acc[k] += __shfl_xor_sync(0xffffffffu, acc[k], off);
        cnt += __shfl_xor_sync(0xffffffffu, cnt, off);
    }
    if (lane == 0) {
        float denom = 1.f / ((float)cnt + 1.f);
        const float* vc = g_value_centers + (bh * M_ + w) * HD_;
        float* dst = g_agg + (bh * M_ + w) * HD_;
#pragma unroll
        for (int k = 0; k < 24; k++)
            dst[k] = (acc[k] + vc[k]) * denom;
    }
}

// =====================================================================
// K5: dispatch + output projection, fused.
// Block: 64 tokens x 128 out channels (z = col half); 256 threads; 8x4/thread.
// Ms stride 96 (a-loads are warp-uniform broadcasts -> no conflict);
// Wp stride 20 -> lane start bank 20l mod 32 distinct, aligned mod 4.
// =====================================================================
__global__ __launch_bounds__(256) void k_out(
    const float* __restrict__ proj_w, const float* __restrict__ proj_b,
    float* __restrict__ out)
{
    __shared__ float agg_sh[HEADS_ * M_ * HD_];   // 1536 floats
    __shared__ float Ms[64][96];                  // merged vectors
    __shared__ float Wp[128][20];                 // proj chunk (16 + pad 4)

    const int bb = blockIdx.y;
    const int n0 = blockIdx.x * 64;
    const int c0 = blockIdx.z * 128;
    const int tid = threadIdx.x;
    const int tx = tid & 31;   // channel lane
    const int ty = tid >> 5;   // warp id

    for (int l = tid; l < 1536; l += 256)
        agg_sh[l] = g_agg[(size_t)bb * 1536 + l];
    __syncthreads();

    {   // build merged vectors: thread -> (token, head)
        int tok = tid >> 2, e = tid & 3;
        int n = n0 + tok;
        size_t ix = (size_t)(bb * HEADS_ + e) * N_ + n;
        int   c = g_assign[ix];
        float s = g_sval[ix];
#pragma unroll
        for (int k = 0; k < 24; k++)
            Ms[tok][e * HD_ + k] = s * agg_sh[(e * M_ + c) * HD_ + k];
    }

    float acc[8][4];
#pragma unroll
    for (int i = 0; i < 8; i++)
#pragma unroll
        for (int j = 0; j < 4; j++) acc[i][j] = 0.f;

    for (int kc = 0; kc < 96; kc += 16) {
        __syncthreads();   // Ms ready (iter 0) / previous Wp consumed
        // load Wp: 128x16 = 512 float4
        for (int l = tid; l < 512; l += 256) {
            int row = l >> 2, q = l & 3;
            *(float4*)&Wp[row][q * 4] =
                *(const float4*)(proj_w + (size_t)(c0 + row) * 96 + kc + q * 4);
        }
        __syncthreads();
#pragma unroll
        for (int kk = 0; kk < 16; kk += 4) {
            float a[8][4], w[4][4];
#pragma unroll
            for (int i = 0; i < 8; i++) {                       // broadcast LDS.128
                float4 t = *(const float4*)&Ms[i * 8 + ty][kc + kk];
                a[i][0] = t.x; a[i][1] = t.y; a[i][2] = t.z; a[i][3] = t.w;
            }
#pragma unroll
            for (int j = 0; j < 4; j++) {                       // conflict-free LDS.128
                float4 t = *(const float4*)&Wp[j * 32 + tx][kk];
                w[j][0] = t.x; w[j][1] = t.y; w[j][2] = t.z; w[j][3] = t.w;
            }
#pragma unroll
            for (int s = 0; s < 4; s++)
#pragma unroll
                for (int i = 0; i < 8; i++)
#pragma unroll
                    for (int j = 0; j < 4; j++)
                        acc[i][j] = fmaf(a[i][s], w[j][s], acc[i][j]);
        }
    }

#pragma unroll
    for (int i = 0; i < 8; i++) {
        int n = n0 + i * 8 + ty;
#pragma unroll
        for (int j = 0; j < 4; j++) {
            int ch = c0 + j * 32 + tx;
            out[((size_t)(bb * N_ + n)) * OUT_ + ch] = acc[i][j] + proj_b[ch];
        }
    }
}

// =====================================================================
extern "C" void kernel_launch(void* const* d_in, const int* in_sizes, int n_in,
                              void* d_out, int out_size)
{
    (void)in_sizes; (void)n_in; (void)out_size;
    const float* x         = (const float*)d_in[0];
    const float* f_w       = (const float*)d_in[1];
    const float* f_b       = (const float*)d_in[2];
    const float* v_w       = (const float*)d_in[3];
    const float* v_b       = (const float*)d_in[4];
    const float* proj_w    = (const float*)d_in[5];
    const float* proj_b    = (const float*)d_in[6];
    const float* sim_alpha = (const float*)d_in[7];
    const float* sim_beta  = (const float*)d_in[8];
    float* out = (float*)d_out;

    k_gemm_fv<<<(B_ * N_) / 64, 256>>>(x, f_w, f_b, v_w, v_b);
    k_pool<<<BH_ * M_, 192>>>();
    k_cluster<<<BH_, 512>>>(sim_alpha, sim_beta);
    dim3 g5(N_ / 64, B_, 2);
    k_out<<<g5, 256>>>(proj_w, proj_b, out);
}

// round 6
// speedup vs baseline: 1.3013x; 1.3013x over previous
#include <cuda_runtime.h>
#include <cuda_bf16.h>
#include <mma.h>
#include <cstdint>
#include <cfloat>

using namespace nvcuda;

// Problem constants
#define B_    64
#define P_    56
#define N_    3136      // P*P
#define DIM_  256
#define HEADS_ 4
#define HD_   24
#define M_    16
#define OUT_  256
#define BH_   256       // B*HEADS

// ---------------- scratch (no allocation; __device__ globals) ----------------
__device__ float g_f[(size_t)BH_ * N_ * HD_];
__device__ float g_v[(size_t)BH_ * N_ * HD_];
__device__ float g_centers_n[BH_ * M_ * HD_];       // EXACT normalized centers
__device__ float g_value_centers[BH_ * M_ * HD_];   // EXACT value centers
__device__ float g_agg[BH_ * M_ * HD_];
__device__ int   g_assign[(size_t)BH_ * N_];
__device__ float g_sval[(size_t)BH_ * N_];

typedef wmma::fragment<wmma::matrix_a, 16, 16, 16, __nv_bfloat16, wmma::row_major> FragA;
typedef wmma::fragment<wmma::matrix_b, 16, 16, 16, __nv_bfloat16, wmma::col_major> FragB;
typedef wmma::fragment<wmma::accumulator, 16, 16, 16, float> FragC;

__device__ __forceinline__ void bsplit(float v, __nv_bfloat16& h, __nv_bfloat16& l) {
    h = __float2bfloat16(v);
    l = __float2bfloat16(v - __bfloat162float(h));
}

// =====================================================================
// K1: fused feat/val GEMM via WMMA bf16 3-term split (round-5 fixed).
// =====================================================================
#define G1_LDA 40   // 32 + 8 pad
__global__ __launch_bounds__(256) void k_gemm_fv_mma(
    const float* __restrict__ x,
    const float* __restrict__ f_w, const float* __restrict__ f_b,
    const float* __restrict__ v_w, const float* __restrict__ v_b)
{
    __shared__ __align__(32) unsigned char pool[36864];
    __nv_bfloat16* Ah = (__nv_bfloat16*)pool;                    // 128*40
    __nv_bfloat16* Al = Ah + 128 * G1_LDA;
    __nv_bfloat16* Bh = Al + 128 * G1_LDA;                       // 64*40
    __nv_bfloat16* Bl = Bh + 64 * G1_LDA;
    float* stage = (float*)pool;                                 // 128 x 72

    const int tid = threadIdx.x;
    const int wid = tid >> 5;
    const int wm = wid & 3;
    const int wn = wid >> 2;
    const int r0 = blockIdx.x * 128;
    const int c0 = blockIdx.y * 64;

    FragC acc[2][2];
#pragma unroll
    for (int mi = 0; mi < 2; mi++)
#pragma unroll
        for (int ni = 0; ni < 2; ni++) wmma::fill_fragment(acc[mi][ni], 0.f);

    for (int kc = 0; kc < DIM_; kc += 32) {
#pragma unroll
        for (int s = tid; s < 1024; s += 256) {
            int row = s >> 3, q = (s & 7) * 4;
            float4 v = *(const float4*)(x + (size_t)(r0 + row) * DIM_ + kc + q);
            __nv_bfloat16 h, l;
            __nv_bfloat16* ah = Ah + row * G1_LDA + q;
            __nv_bfloat16* al = Al + row * G1_LDA + q;
            bsplit(v.x, h, l); ah[0] = h; al[0] = l;
            bsplit(v.y, h, l); ah[1] = h; al[1] = l;
            bsplit(v.z, h, l); ah[2] = h; al[2] = l;
            bsplit(v.w, h, l); ah[3] = h; al[3] = l;
        }
#pragma unroll
        for (int s = tid; s < 512; s += 256) {
            int row = s >> 3, q = (s & 7) * 4;
            int gc = c0 + row;
            const float* src = (gc < 96) ? (f_w + (size_t)gc * DIM_)
                                         : (v_w + (size_t)(gc - 96) * DIM_);
            float4 v = *(const float4*)(src + kc + q);
            __nv_bfloat16 h, l;
            __nv_bfloat16* bh = Bh + row * G1_LDA + q;
            __nv_bfloat16* bl = Bl + row * G1_LDA + q;
            bsplit(v.x, h, l); bh[0] = h; bl[0] = l;
            bsplit(v.y, h, l); bh[1] = h; bl[1] = l;
            bsplit(v.z, h, l); bh[2] = h; bl[2] = l;
            bsplit(v.w, h, l); bh[3] = h; bl[3] = l;
        }
        __syncthreads();

#pragma unroll
        for (int ks = 0; ks < 32; ks += 16) {
            FragA ah[2], al[2];
            FragB bh[2], bl[2];
#pragma unroll
            for (int mi = 0; mi < 2; mi++) {
                wmma::load_matrix_sync(ah[mi], Ah + (wm * 32 + mi * 16) * G1_LDA + ks, G1_LDA);
                wmma::load_matrix_sync(al[mi], Al + (wm * 32 + mi * 16) * G1_LDA + ks, G1_LDA);
            }
#pragma unroll
            for (int ni = 0; ni < 2; ni++) {
                wmma::load_matrix_sync(bh[ni], Bh + (wn * 32 + ni * 16) * G1_LDA + ks, G1_LDA);
                wmma::load_matrix_sync(bl[ni], Bl + (wn * 32 + ni * 16) * G1_LDA + ks, G1_LDA);
            }
#pragma unroll
            for (int mi = 0; mi < 2; mi++)
#pragma unroll
                for (int ni = 0; ni < 2; ni++) {
                    wmma::mma_sync(acc[mi][ni], ah[mi], bh[ni], acc[mi][ni]);
                    wmma::mma_sync(acc[mi][ni], ah[mi], bl[ni], acc[mi][ni]);
                    wmma::mma_sync(acc[mi][ni], al[mi], bh[ni], acc[mi][ni]);
                }
        }
        __syncthreads();
    }

#pragma unroll
    for (int mi = 0; mi < 2; mi++)
#pragma unroll
        for (int ni = 0; ni < 2; ni++)
            wmma::store_matrix_sync(stage + (size_t)(wm * 32 + mi * 16) * 72
                                          + wn * 32 + ni * 16,
                                    acc[mi][ni], 72, wmma::mem_row_major);
    __syncthreads();

#pragma unroll
    for (int i = 0; i < 32; i++) {
        int el = i * 256 + tid;
        int row = el >> 6, lc = el & 63;
        int col = c0 + lc;
        int r = r0 + row;
        int bbr = r / N_;            // per-row batch index (3136 % 128 != 0)
        int n = r - bbr * N_;
        float val = stage[row * 72 + lc];
        if (col < 96) {
            int e = col / HD_, hd = col % HD_;
            g_f[((size_t)(bbr * HEADS_ + e) * N_ + n) * HD_ + hd] = val + f_b[col];
        } else {
            int c2 = col - 96;
            int e = c2 / HD_, hd = c2 % HD_;
            g_v[((size_t)(bbr * HEADS_ + e) * N_ + n) * HD_ + hd] = val + v_b[c2];
        }
    }
}

// =====================================================================
// K2: EXACT centers via linearity:  pooled f = pool(x) @ W^T + bias.
// Block per (b, m) : pool x over 196 tokens (fp32), then 192 dots (warps),
// per-head L2 norm -> g_centers_n ; value part -> g_value_centers.
// =====================================================================
__global__ __launch_bounds__(256) void k_centers(
    const float* __restrict__ x,
    const float* __restrict__ f_w, const float* __restrict__ f_b,
    const float* __restrict__ v_w, const float* __restrict__ v_b)
{
    __shared__ float px[256];
    __shared__ float cf[192];
    __shared__ float ninv[4];

    const int g = blockIdx.x;
    const int b = g >> 4;
    const int m = g & 15;
    const int pw = m >> 2, ph = m & 3;
    const int tid = threadIdx.x;
    const int wid = tid >> 5, lane = tid & 31;

    // pool: channel tid, mean over 196 tokens (exact block mean)
    {
        float s = 0.f;
        const float* xb = x + (size_t)b * N_ * DIM_ + tid;
#pragma unroll 4
        for (int it = 0; it < 196; it++) {
            int dw = it / 14, dh = it % 14;
            int n = (pw * 14 + dw) * P_ + ph * 14 + dh;
            s += xb[(size_t)n * DIM_];
        }
        px[tid] = s * (1.f / 196.f);
    }
    __syncthreads();

    // 192 dots: warp w computes cols w, w+8, ..., w+184 (lane-parallel over d)
    for (int c = 0; c < 24; c++) {
        int col = wid + c * 8;
        const float* wr = (col < 96) ? (f_w + (size_t)col * DIM_)
                                     : (v_w + (size_t)(col - 96) * DIM_);
        float p = 0.f;
#pragma unroll
        for (int j = 0; j < 8; j++)
            p = fmaf(px[lane + j * 32], wr[lane + j * 32], p);
#pragma unroll
        for (int off = 16; off > 0; off >>= 1)
            p += __shfl_xor_sync(0xffffffffu, p, off);
        if (lane == 0)
            cf[col] = p + ((col < 96) ? f_b[col] : v_b[col - 96]);
    }
    __syncthreads();

    if (tid < 4) {
        float ss = 0.f;
#pragma unroll
        for (int k = 0; k < 24; k++) { float t = cf[tid * 24 + k]; ss += t * t; }
        ninv[tid] = 1.f / fmaxf(sqrtf(ss), 1e-12f);
    }
    __syncthreads();

    if (tid < 96) {
        int e = tid / 24, k = tid % 24;
        g_centers_n[((b * HEADS_ + e) * M_ + m) * HD_ + k] = cf[tid] * ninv[e];
    } else if (tid < 192) {
        int c2 = tid - 96;
        int e = c2 / 24, k = c2 % 24;
        g_value_centers[((b * HEADS_ + e) * M_ + m) * HD_ + k] = cf[tid];
    }
}

// =====================================================================
// K3: per-bh clustering with fp32 refinement of near-tie tokens.
// Phase 1: sims from bf16-split g_f, track best/second, flag gap <= Tflag.
// Phase 1.5: warp-cooperative EXACT fp32 recompute (from x) for flagged.
// Phase 2: warp-per-center aggregation (atomic-free).
// =====================================================================
__global__ __launch_bounds__(512) void k_cluster(
    const float* __restrict__ x,
    const float* __restrict__ f_w, const float* __restrict__ f_b,
    const float* __restrict__ sim_alpha, const float* __restrict__ sim_beta)
{
    __shared__ float cn[M_ * HD_];
    __shared__ unsigned char assign_sh[N_];
    __shared__ unsigned char flag_sh[N_];
    __shared__ float sval_sh[N_];

    const int bh  = blockIdx.x;
    const int b   = bh / HEADS_;
    const int e   = bh % HEADS_;
    const int tid = threadIdx.x;
    const int wid = tid >> 5, lane = tid & 31;
    const float alpha = sim_alpha[0];
    const float beta  = sim_beta[0];
    const float Tflag = fabsf(alpha) * 1e-3f + 1e-7f;

    for (int l = tid; l < M_ * HD_; l += 512)
        cn[l] = g_centers_n[bh * M_ * HD_ + l];
    __syncthreads();

    // ---- phase 1: approximate sims + flag near-ties ----
    for (int n = tid; n < N_; n += 512) {
        float fv[24];
        const float4* fp4 = (const float4*)(g_f + ((size_t)bh * N_ + n) * HD_);
#pragma unroll
        for (int q = 0; q < 6; q++) {
            float4 t = fp4[q];
            fv[q * 4 + 0] = t.x; fv[q * 4 + 1] = t.y;
            fv[q * 4 + 2] = t.z; fv[q * 4 + 3] = t.w;
        }
        float ss = 0.f;
#pragma unroll
        for (int k = 0; k < 24; k++) ss += fv[k] * fv[k];
        float inv = 1.f / fmaxf(sqrtf(ss), 1e-12f);

        float best = -FLT_MAX, second = -FLT_MAX;
        int bi = 0;
#pragma unroll
        for (int m = 0; m < M_; m++) {
            float d = 0.f;
#pragma unroll
            for (int k = 0; k < 24; k++) d = fmaf(cn[m * HD_ + k], fv[k], d);
            float t = beta + alpha * (d * inv);
            t = (t >= 0.f) ? t : 0.2f * t;
            if (t > best) { second = best; best = t; bi = m; }
            else if (t > second) second = t;
        }
        assign_sh[n] = (unsigned char)bi;
        sval_sh[n]   = best;
        flag_sh[n]   = (best - second <= Tflag) ? 1 : 0;
        g_assign[(size_t)bh * N_ + n] = bi;
        g_sval[(size_t)bh * N_ + n]   = best;
    }
    __syncthreads();

    // ---- phase 1.5: exact fp32 refinement for flagged tokens ----
    {
        const int nb = wid * 196;           // 3136 / 16 warps
        for (int n = nb; n < nb + 196; n++) {
            if (!flag_sh[n]) continue;
            // exact f slice: fex[k] = sum_d x[b,n,d] * f_w[e*24+k, d] + f_b
            const float* xr = x + ((size_t)b * N_ + n) * DIM_;
            float xr8[8];
#pragma unroll
            for (int j = 0; j < 8; j++) xr8[j] = xr[lane + j * 32];
            float fex[24];
#pragma unroll
            for (int k = 0; k < 24; k++) {
                const float* wr = f_w + (size_t)(e * 24 + k) * DIM_;
                float p = 0.f;
#pragma unroll
                for (int j = 0; j < 8; j++)
                    p = fmaf(xr8[j], wr[lane + j * 32], p);
#pragma unroll
                for (int off = 16; off > 0; off >>= 1)
                    p += __shfl_xor_sync(0xffffffffu, p, off);
                fex[k] = p + f_b[e * 24 + k];
            }
            float ss = 0.f;
#pragma unroll
            for (int k = 0; k < 24; k++) ss += fex[k] * fex[k];
            float inv = 1.f / fmaxf(sqrtf(ss), 1e-12f);

            float t = -FLT_MAX;
            int idx = 1000;
            if (lane < M_) {
                float d = 0.f;
#pragma unroll
                for (int k = 0; k < 24; k++) d = fmaf(cn[lane * HD_ + k], fex[k], d);
                t = beta + alpha * (d * inv);
                t = (t >= 0.f) ? t : 0.2f * t;
                idx = lane;
            }
#pragma unroll
            for (int off = 16; off > 0; off >>= 1) {
                float ot = __shfl_xor_sync(0xffffffffu, t, off);
                int   oi = __shfl_xor_sync(0xffffffffu, idx, off);
                if (ot > t || (ot == t && oi < idx)) { t = ot; idx = oi; }
            }
            if (lane == 0) {
                assign_sh[n] = (unsigned char)idx;
                sval_sh[n]   = t;
                g_assign[(size_t)bh * N_ + n] = idx;
                g_sval[(size_t)bh * N_ + n]   = t;
            }
        }
    }
    __syncthreads();

    // ---- phase 2: warp per center ----
    const int w = wid;
    float acc[24];
#pragma unroll
    for (int k = 0; k < 24; k++) acc[k] = 0.f;
    int cnt = 0;

    for (int n = lane; n < N_; n += 32) {
        if (assign_sh[n] == (unsigned char)w) {
            float s = sval_sh[n];
            const float4* vp4 = (const float4*)(g_v + ((size_t)bh * N_ + n) * HD_);
#pragma unroll
            for (int q = 0; q < 6; q++) {
                float4 t = vp4[q];
                acc[q * 4 + 0] = fmaf(s, t.x, acc[q * 4 + 0]);
                acc[q * 4 + 1] = fmaf(s, t.y, acc[q * 4 + 1]);
                acc[q * 4 + 2] = fmaf(s, t.z, acc[q * 4 + 2]);
                acc[q * 4 + 3] = fmaf(s, t.w, acc[q * 4 + 3]);
            }
            cnt++;
        }
    }
#pragma unroll
    for (int off = 16; off > 0; off >>= 1) {
#pragma unroll
        for (int k = 0; k < 24; k++)
            acc[k] += __shfl_xor_sync(0xffffffffu, acc[k], off);
        cnt += __shfl_xor_sync(0xffffffffu, cnt, off);
    }
    if (lane == 0) {
        float denom = 1.f / ((float)cnt + 1.f);
        const float* vc = g_value_centers + (bh * M_ + w) * HD_;
        float* dst = g_agg + (bh * M_ + w) * HD_;
#pragma unroll
        for (int k = 0; k < 24; k++)
            dst[k] = (acc[k] + vc[k]) * denom;
    }
}

// =====================================================================
// K4: dispatch + output projection via WMMA bf16 3-term split (round-5).
// =====================================================================
#define G2_LDA 104   // 96 + 8
#define G2_LDB 56    // 48 + 8
__global__ __launch_bounds__(128) void k_out_mma(
    const float* __restrict__ proj_w, const float* __restrict__ proj_b,
    float* __restrict__ out)
{
    __shared__ __align__(32) unsigned char pool[40960];
    __nv_bfloat16* Ah = (__nv_bfloat16*)pool;          // 64*104
    __nv_bfloat16* Al = Ah + 64 * G2_LDA;
    __nv_bfloat16* Bh = Al + 64 * G2_LDA;              // 64*56
    __nv_bfloat16* Bl = Bh + 64 * G2_LDB;
    float* stage = (float*)pool;                       // 64 x 72

    const int tid = threadIdx.x;
    const int wid = tid >> 5;
    const int wm = wid & 1;
    const int wn = wid >> 1;
    const int r0 = blockIdx.x * 64;
    const int c0 = blockIdx.y * 64;
    const int bb = r0 / N_;           // 3136 % 64 == 0 -> uniform

    for (int idx = tid; idx < 256; idx += 128) {
        int trow = idx >> 2, e = idx & 3;
        int r = r0 + trow;
        int n = r - bb * N_;
        size_t aix = (size_t)(bb * HEADS_ + e) * N_ + n;
        int   c = g_assign[aix];
        float s = g_sval[aix];
        const float* ag = g_agg + ((size_t)(bb * HEADS_ + e) * M_ + c) * HD_;
        __nv_bfloat16* ah = Ah + trow * G2_LDA + e * HD_;
        __nv_bfloat16* al = Al + trow * G2_LDA + e * HD_;
#pragma unroll
        for (int k = 0; k < 24; k++) {
            __nv_bfloat16 h, l;
            bsplit(s * ag[k], h, l);
            ah[k] = h; al[k] = l;
        }
    }

    FragC acc[2][2];
#pragma unroll
    for (int mi = 0; mi < 2; mi++)
#pragma unroll
        for (int ni = 0; ni < 2; ni++) wmma::fill_fragment(acc[mi][ni], 0.f);

    for (int ch = 0; ch < 2; ch++) {
        const int kc = ch * 48;
#pragma unroll
        for (int s = tid; s < 768; s += 128) {
            int row = s / 12, q = (s % 12) * 4;
            float4 v = *(const float4*)(proj_w + (size_t)(c0 + row) * 96 + kc + q);
            __nv_bfloat16 h, l;
            __nv_bfloat16* bh = Bh + row * G2_LDB + q;
            __nv_bfloat16* bl = Bl + row * G2_LDB + q;
            bsplit(v.x, h, l); bh[0] = h; bl[0] = l;
            bsplit(v.y, h, l); bh[1] = h; bl[1] = l;
            bsplit(v.z, h, l); bh[2] = h; bl[2] = l;
            bsplit(v.w, h, l); bh[3] = h; bl[3] = l;
        }
        __syncthreads();

#pragma unroll
        for (int ks = 0; ks < 48; ks += 16) {
            FragA ah[2], al[2];
            FragB bh[2], bl[2];
#pragma unroll
            for (int mi = 0; mi < 2; mi++) {
                wmma::load_matrix_sync(ah[mi], Ah + (wm * 32 + mi * 16) * G2_LDA + kc + ks, G2_LDA);
                wmma::load_matrix_sync(al[mi], Al + (wm * 32 + mi * 16) * G2_LDA + kc + ks, G2_LDA);
            }
#pragma unroll
            for (int ni = 0; ni < 2; ni++) {
                wmma::load_matrix_sync(bh[ni], Bh + (wn * 32 + ni * 16) * G2_LDB + ks, G2_LDB);
                wmma::load_matrix_sync(bl[ni], Bl + (wn * 32 + ni * 16) * G2_LDB + ks, G2_LDB);
            }
#pragma unroll
            for (int mi = 0; mi < 2; mi++)
#pragma unroll
                for (int ni = 0; ni < 2; ni++) {
                    wmma::mma_sync(acc[mi][ni], ah[mi], bh[ni], acc[mi][ni]);
                    wmma::mma_sync(acc[mi][ni], ah[mi], bl[ni], acc[mi][ni]);
                    wmma::mma_sync(acc[mi][ni], al[mi], bh[ni], acc[mi][ni]);
                }
        }
        __syncthreads();
    }

#pragma unroll
    for (int mi = 0; mi < 2; mi++)
#pragma unroll
        for (int ni = 0; ni < 2; ni++)
            wmma::store_matrix_sync(stage + (size_t)(wm * 32 + mi * 16) * 72
                                          + wn * 32 + ni * 16,
                                    acc[mi][ni], 72, wmma::mem_row_major);
    __syncthreads();

#pragma unroll
    for (int i = 0; i < 32; i++) {
        int el = i * 128 + tid;
        int row = el >> 6, lc = el & 63;
        int r = r0 + row;
        int ch = c0 + lc;
        out[(size_t)r * OUT_ + ch] = stage[row * 72 + lc] + proj_b[ch];
    }
}

// =====================================================================
extern "C" void kernel_launch(void* const* d_in, const int* in_sizes, int n_in,
                              void* d_out, int out_size)
{
    (void)in_sizes; (void)n_in; (void)out_size;
    const float* x         = (const float*)d_in[0];
    const float* f_w       = (const float*)d_in[1];
    const float* f_b       = (const float*)d_in[2];
    const float* v_w       = (const float*)d_in[3];
    const float* v_b       = (const float*)d_in[4];
    const float* proj_w    = (const float*)d_in[5];
    const float* proj_b    = (const float*)d_in[6];
    const float* sim_alpha = (const float*)d_in[7];
    const float* sim_beta  = (const float*)d_in[8];
    float* out = (float*)d_out;

    dim3 g1((B_ * N_) / 128, 3);
    k_gemm_fv_mma<<<g1, 256>>>(x, f_w, f_b, v_w, v_b);
    k_centers<<<B_ * M_, 256>>>(x, f_w, f_b, v_w, v_b);
    k_cluster<<<BH_, 512>>>(x, f_w, f_b, sim_alpha, sim_beta);
    dim3 g2((B_ * N_) / 64, 4);
    k_out_mma<<<g2, 128>>>(proj_w, proj_b, out);
}